// round 2
// baseline (speedup 1.0000x reference)
#include <cuda_runtime.h>
#include <math.h>
#include <stdint.h>

// Problem constants
#define BB   128
#define SS   196
#define KK   512
#define HH   512
#define VV   32000
#define TT   16
#define TOUT 15

// -------- device scratch (no allocations allowed) --------
__device__ float g_keys [(size_t)BB * SS * HH];   // keys_proj  (51.4 MB)
__device__ float g_xe   [BB * TT * HH];           // gathered embeddings
__device__ float g_xproj[BB * TT * HH];           // fc1(emb)
__device__ float g_hall [(TOUT + 1) * BB * HH];   // h history
__device__ float g_attw [BB * SS];                // softmax weights
__device__ float g_rnn  [BB * 2 * HH];            // [x_t , fc0(context)]
__device__ float g_gi   [BB * 3 * HH];
__device__ float g_gh   [BB * 3 * HH];

// -------- tiny utility kernels --------
__global__ void zero_kernel(float* p, int n) {
    int i = blockIdx.x * blockDim.x + threadIdx.x;
    if (i < n) p[i] = 0.0f;
}

__global__ void gather_emb(const int* __restrict__ cap,
                           const float* __restrict__ emb,
                           float* __restrict__ xe) {
    int idx = blockIdx.x * blockDim.x + threadIdx.x;   // over float4s
    const int n4 = BB * TT * (HH / 4);
    if (idx >= n4) return;
    int m  = idx / (HH / 4);
    int e4 = idx % (HH / 4);
    ((float4*)xe)[idx] =
        ((const float4*)(emb + (size_t)cap[m] * HH))[e4];
}

// -------- generic small SGEMM:  C[M,N] = A[M,K] * W[N,K]^T (+bias) --------
// 32x32 block tile, BK=32, 256 threads, 2x2 per thread. All dims % 32 == 0.
__global__ __launch_bounds__(256) void sgemm32(
    const float* __restrict__ A, const float* __restrict__ W,
    const float* __restrict__ bias, float* __restrict__ C,
    int K, int ldc)
{
    __shared__ float As[32][33];
    __shared__ float Ws[32][33];
    const int bm = blockIdx.y << 5, bn = blockIdx.x << 5;
    const int tid = threadIdx.x;
    const int lr = tid >> 3, lc = (tid & 7) << 2;      // loader: row, col4
    const int tx = tid & 15, ty = tid >> 4;            // compute 2x2
    float a00 = 0.f, a01 = 0.f, a10 = 0.f, a11 = 0.f;

    for (int k0 = 0; k0 < K; k0 += 32) {
        float4 av = *(const float4*)(A + (size_t)(bm + lr) * K + k0 + lc);
        float4 wv = *(const float4*)(W + (size_t)(bn + lr) * K + k0 + lc);
        As[lr][lc + 0] = av.x; As[lr][lc + 1] = av.y;
        As[lr][lc + 2] = av.z; As[lr][lc + 3] = av.w;
        Ws[lr][lc + 0] = wv.x; Ws[lr][lc + 1] = wv.y;
        Ws[lr][lc + 2] = wv.z; Ws[lr][lc + 3] = wv.w;
        __syncthreads();
#pragma unroll
        for (int k = 0; k < 32; k++) {
            float x0 = As[ty * 2][k],     x1 = As[ty * 2 + 1][k];
            float y0 = Ws[tx * 2][k],     y1 = Ws[tx * 2 + 1][k];
            a00 += x0 * y0; a01 += x0 * y1;
            a10 += x1 * y0; a11 += x1 * y1;
        }
        __syncthreads();
    }
    const int r0 = bm + ty * 2, c0 = bn + tx * 2;
    const float b0 = bias ? bias[c0] : 0.f;
    const float b1 = bias ? bias[c0 + 1] : 0.f;
    C[(size_t)r0 * ldc + c0]           = a00 + b0;
    C[(size_t)r0 * ldc + c0 + 1]       = a01 + b1;
    C[(size_t)(r0 + 1) * ldc + c0]     = a10 + b0;
    C[(size_t)(r0 + 1) * ldc + c0 + 1] = a11 + b1;
}

// -------- tf32 tensor-core GEMM: C[M,N] = A[M,K] * W[N,K]^T (+bias) --------
// 128x128 block tile, BK=32, 256 threads = 8 warps in 2(m) x 4(n).
// Warp tile 64x32, mma.m16n8k8 tf32, fp32 accumulate.
// remap==0 : C[r*ldc + c]
// remap==1 : fc2 epilogue -> row r = t*128 + b ; C[(b*TOUT + t)*VV + c]
__device__ __forceinline__ uint32_t f2tf32(float x) {
    uint32_t r;
    asm("cvt.rna.tf32.f32 %0, %1;" : "=r"(r) : "f"(x));
    return r;
}

__global__ __launch_bounds__(256) void gemm_tf32(
    const float* __restrict__ A, const float* __restrict__ W,
    const float* __restrict__ bias, float* __restrict__ C,
    int K, int ldc, int remap)
{
    // [k][m] layout, stride 136 -> (m + 8k) mod 32 covers all banks (conflict-free frag loads)
    __shared__ uint32_t As[32][136];
    __shared__ uint32_t Bs[32][136];

    const int bm = blockIdx.y << 7, bn = blockIdx.x << 7;
    const int tid = threadIdx.x;
    const int lane = tid & 31, warp = tid >> 5;
    const int wm = warp & 1, wn = warp >> 1;      // 2 x 4 warp grid
    const int m0 = wm * 64, n0 = wn * 32;
    const int lq = lane >> 2, lr4 = lane & 3;     // quad row / quad lane

    float acc[4][4][4];
#pragma unroll
    for (int mf = 0; mf < 4; mf++)
#pragma unroll
        for (int nf = 0; nf < 4; nf++)
#pragma unroll
            for (int i = 0; i < 4; i++) acc[mf][nf][i] = 0.f;

    const int ldr = tid >> 1;                     // 0..127: tile row loaded by this thread
    const int ldc0 = (tid & 1) << 4;              // 0 or 16: k-offset
    const float* Ap = A + (size_t)(bm + ldr) * K + ldc0;
    const float* Wp = W + (size_t)(bn + ldr) * K + ldc0;

    for (int k0 = 0; k0 < K; k0 += 32) {
#pragma unroll
        for (int j = 0; j < 4; j++) {
            float4 av = *(const float4*)(Ap + k0 + j * 4);
            float4 wv = *(const float4*)(Wp + k0 + j * 4);
            const int kk = ldc0 + j * 4;
            As[kk + 0][ldr] = f2tf32(av.x);
            As[kk + 1][ldr] = f2tf32(av.y);
            As[kk + 2][ldr] = f2tf32(av.z);
            As[kk + 3][ldr] = f2tf32(av.w);
            Bs[kk + 0][ldr] = f2tf32(wv.x);
            Bs[kk + 1][ldr] = f2tf32(wv.y);
            Bs[kk + 2][ldr] = f2tf32(wv.z);
            Bs[kk + 3][ldr] = f2tf32(wv.w);
        }
        __syncthreads();

#pragma unroll
        for (int kf = 0; kf < 4; kf++) {
            const int kb = kf * 8 + lr4;
            uint32_t a[4][4], b[4][2];
#pragma unroll
            for (int mf = 0; mf < 4; mf++) {
                const int mr = m0 + mf * 16 + lq;
                a[mf][0] = As[kb][mr];
                a[mf][1] = As[kb][mr + 8];
                a[mf][2] = As[kb + 4][mr];
                a[mf][3] = As[kb + 4][mr + 8];
            }
#pragma unroll
            for (int nf = 0; nf < 4; nf++) {
                const int nc = n0 + nf * 8 + lq;
                b[nf][0] = Bs[kb][nc];
                b[nf][1] = Bs[kb + 4][nc];
            }
#pragma unroll
            for (int mf = 0; mf < 4; mf++)
#pragma unroll
                for (int nf = 0; nf < 4; nf++) {
                    asm volatile(
                        "mma.sync.aligned.m16n8k8.row.col.f32.tf32.tf32.f32 "
                        "{%0,%1,%2,%3}, {%4,%5,%6,%7}, {%8,%9}, {%0,%1,%2,%3};"
                        : "+f"(acc[mf][nf][0]), "+f"(acc[mf][nf][1]),
                          "+f"(acc[mf][nf][2]), "+f"(acc[mf][nf][3])
                        : "r"(a[mf][0]), "r"(a[mf][1]), "r"(a[mf][2]), "r"(a[mf][3]),
                          "r"(b[nf][0]), "r"(b[nf][1]));
                }
        }
        __syncthreads();
    }

    // epilogue
#pragma unroll
    for (int mf = 0; mf < 4; mf++) {
        const int r0 = bm + m0 + mf * 16 + lq;
        const int r1 = r0 + 8;
        float *crow0, *crow1;
        if (remap == 0) {
            crow0 = C + (size_t)r0 * ldc;
            crow1 = C + (size_t)r1 * ldc;
        } else {
            const int t0 = r0 >> 7, b0 = r0 & 127;
            const int t1 = r1 >> 7, b1 = r1 & 127;
            crow0 = C + (size_t)(b0 * TOUT + t0) * VV;
            crow1 = C + (size_t)(b1 * TOUT + t1) * VV;
        }
#pragma unroll
        for (int nf = 0; nf < 4; nf++) {
            const int c0 = bn + n0 + nf * 8 + (lr4 << 1);
            const float bb0 = bias ? bias[c0] : 0.f;
            const float bb1 = bias ? bias[c0 + 1] : 0.f;
            crow0[c0]     = acc[mf][nf][0] + bb0;
            crow0[c0 + 1] = acc[mf][nf][1] + bb1;
            crow1[c0]     = acc[mf][nf][2] + bb0;
            crow1[c0 + 1] = acc[mf][nf][3] + bb1;
        }
    }
}

// -------- fused attention: q = h@wq^T ; scores = tanh(q+keys)@v ; softmax --------
// one block per batch element b
__global__ __launch_bounds__(256) void attn_kernel(
    const float* __restrict__ h,      // [B,H]
    const float* __restrict__ keys,   // [B,S,H]
    const float* __restrict__ wq,     // [H,H]
    const float* __restrict__ attv,   // [H]
    float* __restrict__ wout)         // [B,S]
{
    const int b = blockIdx.x;
    const int tid = threadIdx.x;
    const int lane = tid & 31, warp = tid >> 5;  // 8 warps
    __shared__ float h_s[HH], q_s[HH], v_s[HH], sc[SS];
    __shared__ float redm[8], reds[8];

    for (int i = tid; i < HH; i += 256) {
        h_s[i] = h[(size_t)b * HH + i];
        v_s[i] = attv[i];
    }
    __syncthreads();

    // q[j] = sum_k h[k]*wq[j,k]
    for (int j = warp; j < HH; j += 8) {
        const float* wr = wq + (size_t)j * HH;
        float s = 0.f;
        for (int k = lane; k < HH; k += 32) s += h_s[k] * wr[k];
#pragma unroll
        for (int o = 16; o; o >>= 1) s += __shfl_xor_sync(0xffffffffu, s, o);
        if (lane == 0) q_s[j] = s;
    }
    __syncthreads();

    // scores[s] = sum_k tanh(q[k]+keys[b,s,k]) * v[k]
    for (int s0 = warp; s0 < SS; s0 += 8) {
        const float* kr = keys + ((size_t)b * SS + s0) * HH;
        float s = 0.f;
        for (int k = lane; k < HH; k += 32) s += tanhf(q_s[k] + kr[k]) * v_s[k];
#pragma unroll
        for (int o = 16; o; o >>= 1) s += __shfl_xor_sync(0xffffffffu, s, o);
        if (lane == 0) sc[s0] = s;
    }
    __syncthreads();

    // softmax over S=196
    float m = -1e30f;
    for (int i = tid; i < SS; i += 256) m = fmaxf(m, sc[i]);
#pragma unroll
    for (int o = 16; o; o >>= 1) m = fmaxf(m, __shfl_xor_sync(0xffffffffu, m, o));
    if (lane == 0) redm[warp] = m;
    __syncthreads();
    m = redm[0];
#pragma unroll
    for (int w = 1; w < 8; w++) m = fmaxf(m, redm[w]);

    float ssum = 0.f;
    for (int i = tid; i < SS; i += 256) {
        float e = __expf(sc[i] - m);
        sc[i] = e;
        ssum += e;
    }
#pragma unroll
    for (int o = 16; o; o >>= 1) ssum += __shfl_xor_sync(0xffffffffu, ssum, o);
    if (lane == 0) reds[warp] = ssum;
    __syncthreads();
    float tot = 0.f;
#pragma unroll
    for (int w = 0; w < 8; w++) tot += reds[w];
    const float inv = 1.0f / tot;
    for (int i = tid; i < SS; i += 256)
        wout[(size_t)b * SS + i] = sc[i] * inv;
}

// -------- fused context + fc0 + concat(x_t) -> rnn_in --------
// one block per b
__global__ __launch_bounds__(256) void ctx_fc0_kernel(
    const float* __restrict__ wattn,  // [B,S]
    const float* __restrict__ feats,  // [B,S,K]
    const float* __restrict__ fc0w,   // [H,K]
    const float* __restrict__ fc0b,   // [H]
    const float* __restrict__ xproj,  // [B,TT,H]
    int t,
    float* __restrict__ rnn_in)       // [B,2H]
{
    const int b = blockIdx.x;
    const int tid = threadIdx.x;
    __shared__ float w_s[SS], ctx_s[KK];

    for (int i = tid; i < SS; i += 256) w_s[i] = wattn[(size_t)b * SS + i];
    __syncthreads();

    // context[k] = sum_s w[s]*feats[b,s,k]   (coalesced across k)
    for (int k = tid; k < KK; k += 256) {
        const float* fb = feats + (size_t)b * SS * KK + k;
        float acc = 0.f;
#pragma unroll 4
        for (int s = 0; s < SS; s++) acc += w_s[s] * fb[(size_t)s * KK];
        ctx_s[k] = acc;
    }
    // x_t -> first half of rnn_in
    for (int i = tid; i < HH; i += 256)
        rnn_in[(size_t)b * 2 * HH + i] = xproj[((size_t)b * TT + t) * HH + i];
    __syncthreads();

    // fc0: rnn_in[b, H+j] = sum_k ctx[k]*fc0w[j,k] + fc0b[j]
    const int lane = tid & 31, warp = tid >> 5;
    for (int j = warp; j < HH; j += 8) {
        const float* wr = fc0w + (size_t)j * KK;
        float s = 0.f;
        for (int k = lane; k < KK; k += 32) s += ctx_s[k] * wr[k];
#pragma unroll
        for (int o = 16; o; o >>= 1) s += __shfl_xor_sync(0xffffffffu, s, o);
        if (lane == 0) rnn_in[(size_t)b * 2 * HH + HH + j] = s + fc0b[j];
    }
}

// -------- GRU gate combine (torch order r,z,n) --------
__global__ void gru_gates(const float* __restrict__ gi,
                          const float* __restrict__ gh,
                          const float* __restrict__ hprev,
                          float* __restrict__ hnew)
{
    const int idx = blockIdx.x * blockDim.x + threadIdx.x;
    if (idx >= BB * HH) return;
    const int b = idx >> 9, i = idx & 511;
    const float* gib = gi + (size_t)b * 3 * HH;
    const float* ghb = gh + (size_t)b * 3 * HH;
    const float r = 1.f / (1.f + __expf(-(gib[i] + ghb[i])));
    const float z = 1.f / (1.f + __expf(-(gib[i + HH] + ghb[i + HH])));
    const float n = tanhf(gib[i + 2 * HH] + r * ghb[i + 2 * HH]);
    hnew[idx] = (1.f - z) * n + z * hprev[idx];
}

// -------- launch --------
extern "C" void kernel_launch(void* const* d_in, const int* in_sizes, int n_in,
                              void* d_out, int out_size)
{
    const float* features = (const float*)d_in[0];
    const int*   captions = (const int*)  d_in[1];
    const float* emb      = (const float*)d_in[2];
    const float* fc1_w    = (const float*)d_in[3];
    const float* fc1_b    = (const float*)d_in[4];
    const float* att_wq   = (const float*)d_in[5];
    const float* att_wk   = (const float*)d_in[6];
    const float* att_v    = (const float*)d_in[7];
    const float* fc0_w    = (const float*)d_in[8];
    const float* fc0_b    = (const float*)d_in[9];
    const float* gru_wih  = (const float*)d_in[10];
    const float* gru_whh  = (const float*)d_in[11];
    const float* gru_bih  = (const float*)d_in[12];
    const float* gru_bhh  = (const float*)d_in[13];
    const float* fc2_w    = (const float*)d_in[14];
    const float* fc2_b    = (const float*)d_in[15];
    float* out = (float*)d_out;

    float *keys, *xe, *xproj, *hall, *attw, *rnn, *gi, *gh;
    cudaGetSymbolAddress((void**)&keys,  g_keys);
    cudaGetSymbolAddress((void**)&xe,    g_xe);
    cudaGetSymbolAddress((void**)&xproj, g_xproj);
    cudaGetSymbolAddress((void**)&hall,  g_hall);
    cudaGetSymbolAddress((void**)&attw,  g_attw);
    cudaGetSymbolAddress((void**)&rnn,   g_rnn);
    cudaGetSymbolAddress((void**)&gi,    g_gi);
    cudaGetSymbolAddress((void**)&gh,    g_gh);

    // h0 = 0
    zero_kernel<<<(BB * HH + 255) / 256, 256>>>(hall, BB * HH);

    // x = fc1(emb[captions])   (fp32: feeds the recurrence)
    gather_emb<<<(BB * TT * (HH / 4) + 255) / 256, 256>>>(captions, emb, xe);
    sgemm32<<<dim3(HH / 32, (BB * TT) / 32), 256>>>(xe, fc1_w, fc1_b, xproj, HH, HH);

    // keys_proj = features @ att_wk^T : (25088,512)x(512,512) on tensor cores
    gemm_tf32<<<dim3(HH / 128, (BB * SS) / 128), 256>>>(
        features, att_wk, nullptr, keys, KK, HH, 0);

    // sequential decode steps (fc2 hoisted out of the loop)
    for (int t = 0; t < TOUT; t++) {
        const float* hprev = hall + (size_t)t * BB * HH;
        float* hnext       = hall + (size_t)(t + 1) * BB * HH;
        attn_kernel<<<BB, 256>>>(hprev, keys, att_wq, att_v, attw);
        ctx_fc0_kernel<<<BB, 256>>>(attw, features, fc0_w, fc0_b, xproj, t, rnn);
        sgemm32<<<dim3((3 * HH) / 32, BB / 32), 256>>>(rnn, gru_wih, gru_bih, gi, 2 * HH, 3 * HH);
        sgemm32<<<dim3((3 * HH) / 32, BB / 32), 256>>>(hprev, gru_whh, gru_bhh, gh, HH, 3 * HH);
        gru_gates<<<(BB * HH + 255) / 256, 256>>>(gi, gh, hprev, hnext);
    }

    // out[b,t,:] = h_all[t+1][b] @ fc2_w^T + fc2_b as ONE (1920,512)x(512,32000)
    // tensor-core GEMM with row-remap epilogue
    gemm_tf32<<<dim3(VV / 128, (TOUT * BB) / 128), 256>>>(
        hall + (size_t)BB * HH, fc2_w, fc2_b, out, HH, 0, 1);
}

// round 8
// speedup vs baseline: 2.4443x; 2.4443x over previous
#include <cuda_runtime.h>
#include <math.h>
#include <stdint.h>

// Problem constants
#define BB   128
#define SS   196
#define KK   512
#define HH   512
#define VV   32000
#define TT   16
#define TOUT 15

// -------- device scratch (no allocations allowed) --------
__device__ float g_keys [(size_t)BB * SS * HH];   // keys_proj (51.4 MB)
__device__ float g_xe   [BB * TT * HH];           // gathered embeddings
__device__ float g_xproj[BB * TT * HH];           // fc1(emb)
__device__ float g_hall [(TOUT + 1) * BB * HH];   // h history
__device__ float g_qall [BB * HH];                // h @ wq^T
__device__ float g_ctx  [BB * HH];                // attention context (K==H)
__device__ float g_fc0  [BB * HH];                // fc0(context)
__device__ float g_gi   [BB * 3 * HH];
__device__ float g_gh   [BB * 3 * HH];

// -------- fast math helpers --------
__device__ __forceinline__ float fast_tanh(float x) {
    // tanh(x) = 1 - 2/(exp(2x)+1); saturates correctly at +-inf
    float e = __expf(2.0f * x);
    return 1.0f - __fdividef(2.0f, e + 1.0f);
}
__device__ __forceinline__ float fast_sigmoid(float x) {
    return __fdividef(1.0f, 1.0f + __expf(-x));
}
__device__ __forceinline__ uint32_t f2tf32(float x) {
    uint32_t r;
    asm("cvt.rna.tf32.f32 %0, %1;" : "=r"(r) : "f"(x));
    return r;
}

// -------- tiny utility kernels --------
__global__ void zero_kernel(float* p, int n) {
    int i = blockIdx.x * blockDim.x + threadIdx.x;
    if (i < n) p[i] = 0.0f;
}

__global__ void gather_emb(const int* __restrict__ cap,
                           const float* __restrict__ emb,
                           float* __restrict__ xe) {
    int idx = blockIdx.x * blockDim.x + threadIdx.x;   // over float4s
    const int n4 = BB * TT * (HH / 4);
    if (idx >= n4) return;
    int m  = idx / (HH / 4);
    int e4 = idx % (HH / 4);
    ((float4*)xe)[idx] = ((const float4*)(emb + (size_t)cap[m] * HH))[e4];
}

// -------- pipelined small SGEMM: C[M,N] = A[M,K] * W[N,K]^T (+bias) --------
// 32x32 tile, BK=32, 256 threads, 2x2 per thread, register prefetch +
// double-buffered smem (one __syncthreads per K-tile).
__global__ __launch_bounds__(256) void sgemm32p(
    const float* __restrict__ A, const float* __restrict__ W,
    const float* __restrict__ bias, float* __restrict__ C,
    int K, int ldc)
{
    __shared__ float As[2][32][33];
    __shared__ float Ws[2][32][33];
    const int bm = blockIdx.y << 5, bn = blockIdx.x << 5;
    const int tid = threadIdx.x;
    const int lr = tid >> 3, lc = (tid & 7) << 2;
    const int tx = tid & 15, ty = tid >> 4;
    const float* Ap = A + (size_t)(bm + lr) * K + lc;
    const float* Wp = W + (size_t)(bn + lr) * K + lc;

    float4 av = *(const float4*)Ap;
    float4 wv = *(const float4*)Wp;
    As[0][lr][lc + 0] = av.x; As[0][lr][lc + 1] = av.y;
    As[0][lr][lc + 2] = av.z; As[0][lr][lc + 3] = av.w;
    Ws[0][lr][lc + 0] = wv.x; Ws[0][lr][lc + 1] = wv.y;
    Ws[0][lr][lc + 2] = wv.z; Ws[0][lr][lc + 3] = wv.w;
    __syncthreads();

    float a00 = 0.f, a01 = 0.f, a10 = 0.f, a11 = 0.f;
    int p = 0;
    for (int k0 = 0; k0 < K; k0 += 32) {
        const int kn = k0 + 32;
        if (kn < K) {                      // issue next-tile loads
            av = *(const float4*)(Ap + kn);
            wv = *(const float4*)(Wp + kn);
        }
#pragma unroll
        for (int k = 0; k < 32; k++) {     // compute hides LDG latency
            float x0 = As[p][ty * 2][k],     x1 = As[p][ty * 2 + 1][k];
            float y0 = Ws[p][tx * 2][k],     y1 = Ws[p][tx * 2 + 1][k];
            a00 += x0 * y0; a01 += x0 * y1;
            a10 += x1 * y0; a11 += x1 * y1;
        }
        if (kn < K) {
            const int q = p ^ 1;
            As[q][lr][lc + 0] = av.x; As[q][lr][lc + 1] = av.y;
            As[q][lr][lc + 2] = av.z; As[q][lr][lc + 3] = av.w;
            Ws[q][lr][lc + 0] = wv.x; Ws[q][lr][lc + 1] = wv.y;
            Ws[q][lr][lc + 2] = wv.z; Ws[q][lr][lc + 3] = wv.w;
            __syncthreads();
            p = q;
        }
    }
    const int r0 = bm + ty * 2, c0 = bn + tx * 2;
    const float b0 = bias ? bias[c0] : 0.f;
    const float b1 = bias ? bias[c0 + 1] : 0.f;
    C[(size_t)r0 * ldc + c0]           = a00 + b0;
    C[(size_t)r0 * ldc + c0 + 1]       = a01 + b1;
    C[(size_t)(r0 + 1) * ldc + c0]     = a10 + b0;
    C[(size_t)(r0 + 1) * ldc + c0 + 1] = a11 + b1;
}

// -------- GRU GEMMs fused into one launch (grid.z: 0=gi, 1=gh) --------
// gi = [x_t | fc0out] @ wih^T + bih   (K=1024, A segmented)
// gh = h @ whh^T + bhh                (K=512)
// double-buffered smem, one sync per K-tile
__global__ __launch_bounds__(256) void gru_gemm(
    const float* __restrict__ xproj, const float* __restrict__ fc0out,
    const float* __restrict__ h,
    const float* __restrict__ wih, const float* __restrict__ whh,
    const float* __restrict__ bih, const float* __restrict__ bhh,
    float* __restrict__ gi, float* __restrict__ gh, int t)
{
    const int z = blockIdx.z;
    const int K = z ? HH : 2 * HH;
    const float* W    = z ? whh : wih;
    const float* bias = z ? bhh : bih;
    float* C          = z ? gh  : gi;

    __shared__ float As[2][32][33];
    __shared__ float Ws[2][32][33];
    const int bm = blockIdx.y << 5, bn = blockIdx.x << 5;
    const int tid = threadIdx.x;
    const int lr = tid >> 3, lc = (tid & 7) << 2;
    const int tx = tid & 15, ty = tid >> 4;

    const int b = bm + lr;
    const float* Arow0 = z ? (h + (size_t)b * HH)
                           : (xproj + ((size_t)b * TT + t) * HH);
    const float* Arow1 = fc0out + (size_t)b * HH;
    const float* Wp = W + (size_t)(bn + lr) * K + lc;

    float4 av = *(const float4*)(Arow0 + lc);
    float4 wv = *(const float4*)Wp;
    As[0][lr][lc + 0] = av.x; As[0][lr][lc + 1] = av.y;
    As[0][lr][lc + 2] = av.z; As[0][lr][lc + 3] = av.w;
    Ws[0][lr][lc + 0] = wv.x; Ws[0][lr][lc + 1] = wv.y;
    Ws[0][lr][lc + 2] = wv.z; Ws[0][lr][lc + 3] = wv.w;
    __syncthreads();

    float a00 = 0.f, a01 = 0.f, a10 = 0.f, a11 = 0.f;
    int p = 0;
    for (int k0 = 0; k0 < K; k0 += 32) {
        const int kn = k0 + 32;
        if (kn < K) {
            const float* ap = (z == 0 && kn >= HH) ? (Arow1 + kn - HH) : (Arow0 + kn);
            av = *(const float4*)(ap + lc);
            wv = *(const float4*)(Wp + kn);
        }
#pragma unroll
        for (int k = 0; k < 32; k++) {
            float x0 = As[p][ty * 2][k],     x1 = As[p][ty * 2 + 1][k];
            float y0 = Ws[p][tx * 2][k],     y1 = Ws[p][tx * 2 + 1][k];
            a00 += x0 * y0; a01 += x0 * y1;
            a10 += x1 * y0; a11 += x1 * y1;
        }
        if (kn < K) {
            const int q = p ^ 1;
            As[q][lr][lc + 0] = av.x; As[q][lr][lc + 1] = av.y;
            As[q][lr][lc + 2] = av.z; As[q][lr][lc + 3] = av.w;
            Ws[q][lr][lc + 0] = wv.x; Ws[q][lr][lc + 1] = wv.y;
            Ws[q][lr][lc + 2] = wv.z; Ws[q][lr][lc + 3] = wv.w;
            __syncthreads();
            p = q;
        }
    }
    const int r0 = bm + ty * 2, c0 = bn + tx * 2;
    const float b0 = bias[c0], b1 = bias[c0 + 1];
    C[(size_t)r0 * (3 * HH) + c0]           = a00 + b0;
    C[(size_t)r0 * (3 * HH) + c0 + 1]       = a01 + b1;
    C[(size_t)(r0 + 1) * (3 * HH) + c0]     = a10 + b0;
    C[(size_t)(r0 + 1) * (3 * HH) + c0 + 1] = a11 + b1;
}

// -------- tf32 tensor-core GEMM, reg-prefetch + double-buffered smem --------
// 128x128 tile, BK=16, 256 threads = 8 warps (2m x 4n), warp tile 64x32.
// Grid: (x = M/128, y = N/128) -> consecutive blocks share the W slab (L2 reuse).
// remap==1: fc2 epilogue row r = t*128 + b -> C[(b*TOUT + t)*VV + c]
__global__ __launch_bounds__(256, 2) void gemm_tf32(
    const float* __restrict__ A, const float* __restrict__ W,
    const float* __restrict__ bias, float* __restrict__ C,
    int K, int ldc, int remap)
{
    __shared__ uint32_t As[2][16][136];
    __shared__ uint32_t Bs[2][16][136];

    const int bm = blockIdx.x << 7, bn = blockIdx.y << 7;
    const int tid = threadIdx.x;
    const int lane = tid & 31, warp = tid >> 5;
    const int wm = warp & 1, wn = warp >> 1;
    const int m0 = wm * 64, n0 = wn * 32;
    const int lq = lane >> 2, lr4 = lane & 3;

    float acc[4][4][4];
#pragma unroll
    for (int mf = 0; mf < 4; mf++)
#pragma unroll
        for (int nf = 0; nf < 4; nf++)
#pragma unroll
            for (int i = 0; i < 4; i++) acc[mf][nf][i] = 0.f;

    const int ldr  = tid >> 1;             // 0..127 tile row
    const int ldc0 = (tid & 1) << 3;       // 0 or 8
    const float* Ap = A + (size_t)(bm + ldr) * K + ldc0;
    const float* Wp = W + (size_t)(bn + ldr) * K + ldc0;

    // preload K-tile 0 into buffer 0
    {
        float4 pa0 = *(const float4*)Ap,  pa1 = *(const float4*)(Ap + 4);
        float4 pw0 = *(const float4*)Wp,  pw1 = *(const float4*)(Wp + 4);
        As[0][ldc0 + 0][ldr] = f2tf32(pa0.x); As[0][ldc0 + 1][ldr] = f2tf32(pa0.y);
        As[0][ldc0 + 2][ldr] = f2tf32(pa0.z); As[0][ldc0 + 3][ldr] = f2tf32(pa0.w);
        As[0][ldc0 + 4][ldr] = f2tf32(pa1.x); As[0][ldc0 + 5][ldr] = f2tf32(pa1.y);
        As[0][ldc0 + 6][ldr] = f2tf32(pa1.z); As[0][ldc0 + 7][ldr] = f2tf32(pa1.w);
        Bs[0][ldc0 + 0][ldr] = f2tf32(pw0.x); Bs[0][ldc0 + 1][ldr] = f2tf32(pw0.y);
        Bs[0][ldc0 + 2][ldr] = f2tf32(pw0.z); Bs[0][ldc0 + 3][ldr] = f2tf32(pw0.w);
        Bs[0][ldc0 + 4][ldr] = f2tf32(pw1.x); Bs[0][ldc0 + 5][ldr] = f2tf32(pw1.y);
        Bs[0][ldc0 + 6][ldr] = f2tf32(pw1.z); Bs[0][ldc0 + 7][ldr] = f2tf32(pw1.w);
    }
    __syncthreads();

    int p = 0;
    for (int k0 = 0; k0 < K; k0 += 16) {
        const int kn = k0 + 16;
        float4 pa0, pa1, pw0, pw1;
        if (kn < K) {                       // issue next-tile loads
            pa0 = *(const float4*)(Ap + kn);  pa1 = *(const float4*)(Ap + kn + 4);
            pw0 = *(const float4*)(Wp + kn);  pw1 = *(const float4*)(Wp + kn + 4);
        }
        // compute current buffer (hides LDG latency)
#pragma unroll
        for (int kf = 0; kf < 2; kf++) {
            const int kb = kf * 8 + lr4;
            uint32_t a[4][4], b[4][2];
#pragma unroll
            for (int mf = 0; mf < 4; mf++) {
                const int mr = m0 + mf * 16 + lq;
                a[mf][0] = As[p][kb][mr];
                a[mf][1] = As[p][kb][mr + 8];
                a[mf][2] = As[p][kb + 4][mr];
                a[mf][3] = As[p][kb + 4][mr + 8];
            }
#pragma unroll
            for (int nf = 0; nf < 4; nf++) {
                const int nc = n0 + nf * 8 + lq;
                b[nf][0] = Bs[p][kb][nc];
                b[nf][1] = Bs[p][kb + 4][nc];
            }
#pragma unroll
            for (int mf = 0; mf < 4; mf++)
#pragma unroll
                for (int nf = 0; nf < 4; nf++) {
                    asm volatile(
                        "mma.sync.aligned.m16n8k8.row.col.f32.tf32.tf32.f32 "
                        "{%0,%1,%2,%3}, {%4,%5,%6,%7}, {%8,%9}, {%0,%1,%2,%3};"
                        : "+f"(acc[mf][nf][0]), "+f"(acc[mf][nf][1]),
                          "+f"(acc[mf][nf][2]), "+f"(acc[mf][nf][3])
                        : "r"(a[mf][0]), "r"(a[mf][1]), "r"(a[mf][2]), "r"(a[mf][3]),
                          "r"(b[nf][0]), "r"(b[nf][1]));
                }
        }
        if (kn < K) {                       // store into other buffer, single sync
            const int q = p ^ 1;
            As[q][ldc0 + 0][ldr] = f2tf32(pa0.x); As[q][ldc0 + 1][ldr] = f2tf32(pa0.y);
            As[q][ldc0 + 2][ldr] = f2tf32(pa0.z); As[q][ldc0 + 3][ldr] = f2tf32(pa0.w);
            As[q][ldc0 + 4][ldr] = f2tf32(pa1.x); As[q][ldc0 + 5][ldr] = f2tf32(pa1.y);
            As[q][ldc0 + 6][ldr] = f2tf32(pa1.z); As[q][ldc0 + 7][ldr] = f2tf32(pa1.w);
            Bs[q][ldc0 + 0][ldr] = f2tf32(pw0.x); Bs[q][ldc0 + 1][ldr] = f2tf32(pw0.y);
            Bs[q][ldc0 + 2][ldr] = f2tf32(pw0.z); Bs[q][ldc0 + 3][ldr] = f2tf32(pw0.w);
            Bs[q][ldc0 + 4][ldr] = f2tf32(pw1.x); Bs[q][ldc0 + 5][ldr] = f2tf32(pw1.y);
            Bs[q][ldc0 + 6][ldr] = f2tf32(pw1.z); Bs[q][ldc0 + 7][ldr] = f2tf32(pw1.w);
            __syncthreads();
            p = q;
        }
    }

#pragma unroll
    for (int mf = 0; mf < 4; mf++) {
        const int r0 = bm + m0 + mf * 16 + lq;
        const int r1 = r0 + 8;
        float *crow0, *crow1;
        if (remap == 0) {
            crow0 = C + (size_t)r0 * ldc;
            crow1 = C + (size_t)r1 * ldc;
        } else {
            const int t0 = r0 >> 7, b0 = r0 & 127;
            const int t1 = r1 >> 7, b1 = r1 & 127;
            crow0 = C + (size_t)(b0 * TOUT + t0) * VV;
            crow1 = C + (size_t)(b1 * TOUT + t1) * VV;
        }
#pragma unroll
        for (int nf = 0; nf < 4; nf++) {
            const int c0 = bn + n0 + nf * 8 + (lr4 << 1);
            const float bb0 = bias ? bias[c0] : 0.f;
            const float bb1 = bias ? bias[c0 + 1] : 0.f;
            *(float2*)&crow0[c0] = make_float2(acc[mf][nf][0] + bb0, acc[mf][nf][1] + bb1);
            *(float2*)&crow1[c0] = make_float2(acc[mf][nf][2] + bb0, acc[mf][nf][3] + bb1);
        }
    }
}

// -------- attention scores + softmax + context (one block per b, 512 thr) ----
__global__ __launch_bounds__(512) void attn_ctx(
    const float* __restrict__ qall,   // [B,H] = h @ wq^T
    const float* __restrict__ keys,   // [B,S,H]
    const float* __restrict__ feats,  // [B,S,K]
    const float* __restrict__ attv,   // [H]
    float* __restrict__ ctx)          // [B,K]
{
    const int b = blockIdx.x;
    const int tid = threadIdx.x;
    const int lane = tid & 31, warp = tid >> 5;     // 16 warps
    __shared__ float q_s[HH], v_s[HH], sc[SS];
    __shared__ float red[16];

    q_s[tid] = qall[(size_t)b * HH + tid];
    v_s[tid] = attv[tid];
    __syncthreads();

    // scores: each warp handles row pairs (s0, s0+1) for ILP
    for (int s0 = warp * 2; s0 < SS; s0 += 32) {
        const float* kr = keys + ((size_t)b * SS + s0) * HH;
        float acc0 = 0.f, acc1 = 0.f;
        for (int k = lane; k < HH; k += 32) {
            const float q = q_s[k], vv = v_s[k];
            acc0 += fast_tanh(q + kr[k]) * vv;
            acc1 += fast_tanh(q + kr[HH + k]) * vv;
        }
#pragma unroll
        for (int o = 16; o; o >>= 1) {
            acc0 += __shfl_xor_sync(0xffffffffu, acc0, o);
            acc1 += __shfl_xor_sync(0xffffffffu, acc1, o);
        }
        if (lane == 0) { sc[s0] = acc0; sc[s0 + 1] = acc1; }
    }
    __syncthreads();

    // softmax over S=196 (single pass: 512 threads >= S)
    float m = (tid < SS) ? sc[tid] : -1e30f;
#pragma unroll
    for (int o = 16; o; o >>= 1) m = fmaxf(m, __shfl_xor_sync(0xffffffffu, m, o));
    if (lane == 0) red[warp] = m;
    __syncthreads();
    m = red[0];
#pragma unroll
    for (int w = 1; w < 16; w++) m = fmaxf(m, red[w]);

    float e = (tid < SS) ? __expf(sc[tid] - m) : 0.f;
    float ssum = e;
#pragma unroll
    for (int o = 16; o; o >>= 1) ssum += __shfl_xor_sync(0xffffffffu, ssum, o);
    __syncthreads();               // red[] reuse
    if (lane == 0) red[warp] = ssum;
    __syncthreads();
    float tot = 0.f;
#pragma unroll
    for (int w = 0; w < 16; w++) tot += red[w];
    const float inv = __fdividef(1.0f, tot);
    if (tid < SS) sc[tid] = e * inv;
    __syncthreads();

    // context[k] = sum_s w[s] * feats[b,s,k]   (tid == k, coalesced lines)
    const float* fb = feats + (size_t)b * SS * KK + tid;
    float acc = 0.f;
#pragma unroll 14
    for (int s = 0; s < SS; s++) acc += sc[s] * fb[(size_t)s * KK];
    ctx[(size_t)b * KK + tid] = acc;
}

// -------- GRU gate combine (torch order r,z,n) --------
__global__ void gru_gates(const float* __restrict__ gi,
                          const float* __restrict__ gh,
                          const float* __restrict__ hprev,
                          float* __restrict__ hnew)
{
    const int idx = blockIdx.x * blockDim.x + threadIdx.x;
    if (idx >= BB * HH) return;
    const int b = idx >> 9, i = idx & 511;
    const float* gib = gi + (size_t)b * 3 * HH;
    const float* ghb = gh + (size_t)b * 3 * HH;
    const float r = fast_sigmoid(gib[i] + ghb[i]);
    const float z = fast_sigmoid(gib[i + HH] + ghb[i + HH]);
    const float n = fast_tanh(gib[i + 2 * HH] + r * ghb[i + 2 * HH]);
    hnew[idx] = (1.f - z) * n + z * hprev[idx];
}

// -------- launch --------
extern "C" void kernel_launch(void* const* d_in, const int* in_sizes, int n_in,
                              void* d_out, int out_size)
{
    const float* features = (const float*)d_in[0];
    const int*   captions = (const int*)  d_in[1];
    const float* emb      = (const float*)d_in[2];
    const float* fc1_w    = (const float*)d_in[3];
    const float* fc1_b    = (const float*)d_in[4];
    const float* att_wq   = (const float*)d_in[5];
    const float* att_wk   = (const float*)d_in[6];
    const float* att_v    = (const float*)d_in[7];
    const float* fc0_w    = (const float*)d_in[8];
    const float* fc0_b    = (const float*)d_in[9];
    const float* gru_wih  = (const float*)d_in[10];
    const float* gru_whh  = (const float*)d_in[11];
    const float* gru_bih  = (const float*)d_in[12];
    const float* gru_bhh  = (const float*)d_in[13];
    const float* fc2_w    = (const float*)d_in[14];
    const float* fc2_b    = (const float*)d_in[15];
    float* out = (float*)d_out;

    float *keys, *xe, *xproj, *hall, *qall, *ctx, *fc0o, *gi, *gh;
    cudaGetSymbolAddress((void**)&keys,  g_keys);
    cudaGetSymbolAddress((void**)&xe,    g_xe);
    cudaGetSymbolAddress((void**)&xproj, g_xproj);
    cudaGetSymbolAddress((void**)&hall,  g_hall);
    cudaGetSymbolAddress((void**)&qall,  g_qall);
    cudaGetSymbolAddress((void**)&ctx,   g_ctx);
    cudaGetSymbolAddress((void**)&fc0o,  g_fc0);
    cudaGetSymbolAddress((void**)&gi,    g_gi);
    cudaGetSymbolAddress((void**)&gh,    g_gh);

    // h0 = 0
    zero_kernel<<<(BB * HH + 255) / 256, 256>>>(hall, BB * HH);

    // x = fc1(emb[captions])
    gather_emb<<<(BB * TT * (HH / 4) + 255) / 256, 256>>>(captions, emb, xe);
    sgemm32p<<<dim3(HH / 32, (BB * TT) / 32), 256>>>(xe, fc1_w, fc1_b, xproj, HH, HH);

    // keys_proj = features @ att_wk^T : (25088,512)x(512,512), tensor cores
    gemm_tf32<<<dim3((BB * SS) / 128, HH / 128), 256>>>(
        features, att_wk, nullptr, keys, KK, HH, 0);

    // sequential decode (fc2 hoisted out of the loop)
    for (int t = 0; t < TOUT; t++) {
        const float* hprev = hall + (size_t)t * BB * HH;
        float* hnext       = hall + (size_t)(t + 1) * BB * HH;
        // q = h @ wq^T, batched (weights read once)
        sgemm32p<<<dim3(HH / 32, BB / 32), 256>>>(hprev, att_wq, nullptr, qall, HH, HH);
        // scores + softmax + context
        attn_ctx<<<BB, 512>>>(qall, keys, features, att_v, ctx);
        // fc0(context), batched
        sgemm32p<<<dim3(HH / 32, BB / 32), 256>>>(ctx, fc0_w, fc0_b, fc0o, KK, HH);
        // gi & gh in one launch
        gru_gemm<<<dim3((3 * HH) / 32, BB / 32, 2), 256>>>(
            xproj, fc0o, hprev, gru_wih, gru_whh, gru_bih, gru_bhh, gi, gh, t);
        gru_gates<<<(BB * HH + 255) / 256, 256>>>(gi, gh, hprev, hnext);
    }

    // out = h_all[1..15] @ fc2_w^T + fc2_b as ONE (1920,512)x(512,32000) GEMM
    gemm_tf32<<<dim3((TOUT * BB) / 128, VV / 128), 256>>>(
        hall + (size_t)BB * HH, fc2_w, fc2_b, out, HH, 0, 1);
}

// round 12
// speedup vs baseline: 2.4541x; 1.0040x over previous
#include <cuda_runtime.h>
#include <math.h>
#include <stdint.h>

// Problem constants
#define BB   128
#define SS   196
#define KK   512
#define HH   512
#define VV   32000
#define TT   16
#define TOUT 15
#define G3   (3 * HH)          // 1536

// -------- device scratch (no allocations allowed) --------
__device__ float g_keys [(size_t)BB * SS * HH];   // keys_proj (51.4 MB)
__device__ float g_xe   [BB * TT * HH];           // gathered embeddings
__device__ float g_xproj[BB * TT * HH];           // fc1(emb)
__device__ float g_hall [(TOUT + 1) * BB * HH];   // h history
__device__ float g_ctx  [BB * HH];                // attention context (K==H)
__device__ float g_fc0wT[HH * KK];                // fc0_w transposed
__device__ float g_wcomb[G3 * KK];                // Wih_c @ fc0_w  (1536x512)
__device__ float g_bcomb[G3];                     // Wih_c @ fc0_b
__device__ float g_gix  [(size_t)BB * TT * G3];   // xproj @ Wih_x^T + bih (12.6MB)
__device__ float g_gi   [BB * G3];
__device__ float g_gh   [BB * G3];

// -------- fast math helpers --------
__device__ __forceinline__ float fast_tanh(float x) {
    float e = __expf(2.0f * x);
    return 1.0f - __fdividef(2.0f, e + 1.0f);
}
__device__ __forceinline__ float fast_sigmoid(float x) {
    return __fdividef(1.0f, 1.0f + __expf(-x));
}
__device__ __forceinline__ uint32_t f2tf32(float x) {
    uint32_t r;
    asm("cvt.rna.tf32.f32 %0, %1;" : "=r"(r) : "f"(x));
    return r;
}

// -------- tiny utility kernels --------
__global__ void zero_kernel(float* p, int n) {
    int i = blockIdx.x * blockDim.x + threadIdx.x;
    if (i < n) p[i] = 0.0f;
}

__global__ void gather_emb(const int* __restrict__ cap,
                           const float* __restrict__ emb,
                           float* __restrict__ xe) {
    int idx = blockIdx.x * blockDim.x + threadIdx.x;
    const int n4 = BB * TT * (HH / 4);
    if (idx >= n4) return;
    int m  = idx / (HH / 4);
    int e4 = idx % (HH / 4);
    ((float4*)xe)[idx] = ((const float4*)(emb + (size_t)cap[m] * HH))[e4];
}

// 512x512 transpose (for fc0_w)
__global__ void transpose512(const float* __restrict__ in, float* __restrict__ out) {
    __shared__ float tile[32][33];
    int x = blockIdx.x * 32 + threadIdx.x;
    int y = blockIdx.y * 32 + threadIdx.y;
#pragma unroll
    for (int i = 0; i < 32; i += 8)
        tile[threadIdx.y + i][threadIdx.x] = in[(size_t)(y + i) * 512 + x];
    __syncthreads();
    x = blockIdx.y * 32 + threadIdx.x;
    y = blockIdx.x * 32 + threadIdx.y;
#pragma unroll
    for (int i = 0; i < 32; i += 8)
        out[(size_t)(y + i) * 512 + x] = tile[threadIdx.x][threadIdx.y + i];
}

// bcomb[n] = sum_j Wih_c[n][j] * fc0_b[j]   (Wih_c = gru_wih[:, 512:1024])
__global__ void bcomb_kernel(const float* __restrict__ wih,
                             const float* __restrict__ fc0b,
                             float* __restrict__ bcomb) {
    const int n = blockIdx.x * 4 + (threadIdx.x >> 5);
    const int lane = threadIdx.x & 31;
    if (n >= G3) return;
    const float* row = wih + (size_t)n * (2 * HH) + HH;
    float s = 0.f;
    for (int j = lane; j < HH; j += 32) s += row[j] * fc0b[j];
#pragma unroll
    for (int o = 16; o; o >>= 1) s += __shfl_xor_sync(0xffffffffu, s, o);
    if (lane == 0) bcomb[n] = s;
}

// -------- pipelined fp32 SGEMM: C[M,N] = A[M,K] * W[N,K]^T (+bias) --------
// 32x32 tile, BK=32, 256 threads, 2x2/thread, reg prefetch + dbl-buffered smem.
// lda/ldw = row strides of A/W; ldc = row stride of C.
__global__ __launch_bounds__(256) void sgemm32p(
    const float* __restrict__ A, const float* __restrict__ W,
    const float* __restrict__ bias, float* __restrict__ C,
    int K, int lda, int ldw, int ldc)
{
    __shared__ float As[2][32][33];
    __shared__ float Ws[2][32][33];
    const int bm = blockIdx.y << 5, bn = blockIdx.x << 5;
    const int tid = threadIdx.x;
    const int lr = tid >> 3, lc = (tid & 7) << 2;
    const int tx = tid & 15, ty = tid >> 4;
    const float* Ap = A + (size_t)(bm + lr) * lda + lc;
    const float* Wp = W + (size_t)(bn + lr) * ldw + lc;

    float4 av = *(const float4*)Ap;
    float4 wv = *(const float4*)Wp;
    As[0][lr][lc + 0] = av.x; As[0][lr][lc + 1] = av.y;
    As[0][lr][lc + 2] = av.z; As[0][lr][lc + 3] = av.w;
    Ws[0][lr][lc + 0] = wv.x; Ws[0][lr][lc + 1] = wv.y;
    Ws[0][lr][lc + 2] = wv.z; Ws[0][lr][lc + 3] = wv.w;
    __syncthreads();

    float a00 = 0.f, a01 = 0.f, a10 = 0.f, a11 = 0.f;
    int p = 0;
    for (int k0 = 0; k0 < K; k0 += 32) {
        const int kn = k0 + 32;
        if (kn < K) {
            av = *(const float4*)(Ap + kn);
            wv = *(const float4*)(Wp + kn);
        }
#pragma unroll
        for (int k = 0; k < 32; k++) {
            float x0 = As[p][ty * 2][k],     x1 = As[p][ty * 2 + 1][k];
            float y0 = Ws[p][tx * 2][k],     y1 = Ws[p][tx * 2 + 1][k];
            a00 += x0 * y0; a01 += x0 * y1;
            a10 += x1 * y0; a11 += x1 * y1;
        }
        if (kn < K) {
            const int q = p ^ 1;
            As[q][lr][lc + 0] = av.x; As[q][lr][lc + 1] = av.y;
            As[q][lr][lc + 2] = av.z; As[q][lr][lc + 3] = av.w;
            Ws[q][lr][lc + 0] = wv.x; Ws[q][lr][lc + 1] = wv.y;
            Ws[q][lr][lc + 2] = wv.z; Ws[q][lr][lc + 3] = wv.w;
            __syncthreads();
            p = q;
        }
    }
    const int r0 = bm + ty * 2, c0 = bn + tx * 2;
    const float b0 = bias ? bias[c0] : 0.f;
    const float b1 = bias ? bias[c0 + 1] : 0.f;
    C[(size_t)r0 * ldc + c0]           = a00 + b0;
    C[(size_t)r0 * ldc + c0 + 1]       = a01 + b1;
    C[(size_t)(r0 + 1) * ldc + c0]     = a10 + b0;
    C[(size_t)(r0 + 1) * ldc + c0 + 1] = a11 + b1;
}

// -------- per-step fused GRU GEMMs (grid.z: 0 -> gi, 1 -> gh) --------
// z=0: gi = ctx @ wcomb^T + gix[b*TT+t] + bcomb     (K=512)
// z=1: gh = h   @ whh^T   + bhh                     (K=512)
__global__ __launch_bounds__(256) void step_gemm(
    const float* __restrict__ ctx, const float* __restrict__ h,
    const float* __restrict__ wcomb, const float* __restrict__ whh,
    const float* __restrict__ bcomb, const float* __restrict__ bhh,
    const float* __restrict__ gix, int t,
    float* __restrict__ gi, float* __restrict__ gh)
{
    const int z = blockIdx.z;
    const float* A = z ? h    : ctx;    // [128, 512]
    const float* W = z ? whh  : wcomb;  // [1536, 512]

    __shared__ float As[2][32][33];
    __shared__ float Ws[2][32][33];
    const int bm = blockIdx.y << 5, bn = blockIdx.x << 5;
    const int tid = threadIdx.x;
    const int lr = tid >> 3, lc = (tid & 7) << 2;
    const int tx = tid & 15, ty = tid >> 4;
    const float* Ap = A + (size_t)(bm + lr) * KK + lc;
    const float* Wp = W + (size_t)(bn + lr) * KK + lc;

    float4 av = *(const float4*)Ap;
    float4 wv = *(const float4*)Wp;
    As[0][lr][lc + 0] = av.x; As[0][lr][lc + 1] = av.y;
    As[0][lr][lc + 2] = av.z; As[0][lr][lc + 3] = av.w;
    Ws[0][lr][lc + 0] = wv.x; Ws[0][lr][lc + 1] = wv.y;
    Ws[0][lr][lc + 2] = wv.z; Ws[0][lr][lc + 3] = wv.w;
    __syncthreads();

    float a00 = 0.f, a01 = 0.f, a10 = 0.f, a11 = 0.f;
    int p = 0;
    for (int k0 = 0; k0 < KK; k0 += 32) {
        const int kn = k0 + 32;
        if (kn < KK) {
            av = *(const float4*)(Ap + kn);
            wv = *(const float4*)(Wp + kn);
        }
#pragma unroll
        for (int k = 0; k < 32; k++) {
            float x0 = As[p][ty * 2][k],     x1 = As[p][ty * 2 + 1][k];
            float y0 = Ws[p][tx * 2][k],     y1 = Ws[p][tx * 2 + 1][k];
            a00 += x0 * y0; a01 += x0 * y1;
            a10 += x1 * y0; a11 += x1 * y1;
        }
        if (kn < KK) {
            const int q = p ^ 1;
            As[q][lr][lc + 0] = av.x; As[q][lr][lc + 1] = av.y;
            As[q][lr][lc + 2] = av.z; As[q][lr][lc + 3] = av.w;
            Ws[q][lr][lc + 0] = wv.x; Ws[q][lr][lc + 1] = wv.y;
            Ws[q][lr][lc + 2] = wv.z; Ws[q][lr][lc + 3] = wv.w;
            __syncthreads();
            p = q;
        }
    }
    const int r0 = bm + ty * 2, c0 = bn + tx * 2;
    if (z) {
        const float b0 = bhh[c0], b1 = bhh[c0 + 1];
        gh[(size_t)r0 * G3 + c0]           = a00 + b0;
        gh[(size_t)r0 * G3 + c0 + 1]       = a01 + b1;
        gh[(size_t)(r0 + 1) * G3 + c0]     = a10 + b0;
        gh[(size_t)(r0 + 1) * G3 + c0 + 1] = a11 + b1;
    } else {
        const float b0 = bcomb[c0], b1 = bcomb[c0 + 1];
        const float* gx0 = gix + ((size_t)r0 * TT + t) * G3;
        const float* gx1 = gix + ((size_t)(r0 + 1) * TT + t) * G3;
        gi[(size_t)r0 * G3 + c0]           = a00 + b0 + gx0[c0];
        gi[(size_t)r0 * G3 + c0 + 1]       = a01 + b1 + gx0[c0 + 1];
        gi[(size_t)(r0 + 1) * G3 + c0]     = a10 + b0 + gx1[c0];
        gi[(size_t)(r0 + 1) * G3 + c0 + 1] = a11 + b1 + gx1[c0 + 1];
    }
}

// -------- tf32 tensor-core GEMM, fragment-major smem (LDS.128 / LDS.64) ----
// 128x128 tile, BK=16, 256 threads = 8 warps (2m x 4n), warp tile 64x32.
// A frag quad (kb,mr),(kb,mr+8),(kb+4,mr),(kb+4,mr+8) stored contiguously;
// B frag pair (kb,nc),(kb+4,nc) stored contiguously. Stride 264 words is
// bank-conflict-free per LDS.128/LDS.64 phase.
#define AJ 264
__device__ __forceinline__ int a_addr(int k, int m) {
    return ((k >> 3) * 4 + (k & 3)) * AJ
         + (((m >> 4) * 8 + (m & 7)) << 2)
         + (((k >> 2) & 1) * 2 + ((m >> 3) & 1));
}
__device__ __forceinline__ int b_addr(int k, int n) {
    return ((k >> 3) * 4 + (k & 3)) * AJ + n * 2 + ((k >> 2) & 1);
}

__global__ __launch_bounds__(256, 2) void gemm_tf32(
    const float* __restrict__ A, const float* __restrict__ W,
    const float* __restrict__ bias, float* __restrict__ C,
    int K, int ldc, int remap)
{
    __shared__ __align__(16) uint32_t As[2][8 * AJ];
    __shared__ __align__(16) uint32_t Bs[2][8 * AJ];

    const int bm = blockIdx.x << 7, bn = blockIdx.y << 7;
    const int tid = threadIdx.x;
    const int lane = tid & 31, warp = tid >> 5;
    const int wm = warp & 1, wn = warp >> 1;
    const int m0 = wm * 64, n0 = wn * 32;
    const int lq = lane >> 2, lr4 = lane & 3;

    float acc[4][4][4];
#pragma unroll
    for (int mf = 0; mf < 4; mf++)
#pragma unroll
        for (int nf = 0; nf < 4; nf++)
#pragma unroll
            for (int i = 0; i < 4; i++) acc[mf][nf][i] = 0.f;

    const int ldr  = tid >> 1;             // 0..127 tile row
    const int ldc0 = (tid & 1) << 3;       // 0 or 8
    const float* Ap = A + (size_t)(bm + ldr) * K + ldc0;
    const float* Wp = W + (size_t)(bn + ldr) * K + ldc0;

    // precompute fragment read bases (depend only on lane/warp)
    const int a_rd0 = lr4 * AJ + ((wm * 4) * 8 + lq) * 4;        // + mf*32, + kf*4*AJ
    const int b_rd0 = lr4 * AJ + (n0 + lq) * 2;                   // + nf*16, + kf*4*AJ

    // preload K-tile 0 into buffer 0
    {
        float4 pa0 = *(const float4*)Ap,  pa1 = *(const float4*)(Ap + 4);
        float4 pw0 = *(const float4*)Wp,  pw1 = *(const float4*)(Wp + 4);
        float a8[8] = {pa0.x, pa0.y, pa0.z, pa0.w, pa1.x, pa1.y, pa1.z, pa1.w};
        float w8[8] = {pw0.x, pw0.y, pw0.z, pw0.w, pw1.x, pw1.y, pw1.z, pw1.w};
#pragma unroll
        for (int i = 0; i < 8; i++) {
            As[0][a_addr(ldc0 + i, ldr)] = f2tf32(a8[i]);
            Bs[0][b_addr(ldc0 + i, ldr)] = f2tf32(w8[i]);
        }
    }
    __syncthreads();

    int p = 0;
    for (int k0 = 0; k0 < K; k0 += 16) {
        const int kn = k0 + 16;
        float4 pa0, pa1, pw0, pw1;
        if (kn < K) {
            pa0 = *(const float4*)(Ap + kn);  pa1 = *(const float4*)(Ap + kn + 4);
            pw0 = *(const float4*)(Wp + kn);  pw1 = *(const float4*)(Wp + kn + 4);
        }
#pragma unroll
        for (int kf = 0; kf < 2; kf++) {
            const int abase = kf * 4 * AJ + a_rd0;
            const int bbase = kf * 4 * AJ + b_rd0;
            uint4 a4[4];
            uint2 b2[4];
#pragma unroll
            for (int mf = 0; mf < 4; mf++)
                a4[mf] = *(const uint4*)&As[p][abase + mf * 32];
#pragma unroll
            for (int nf = 0; nf < 4; nf++)
                b2[nf] = *(const uint2*)&Bs[p][bbase + nf * 16];
#pragma unroll
            for (int mf = 0; mf < 4; mf++)
#pragma unroll
                for (int nf = 0; nf < 4; nf++) {
                    asm volatile(
                        "mma.sync.aligned.m16n8k8.row.col.f32.tf32.tf32.f32 "
                        "{%0,%1,%2,%3}, {%4,%5,%6,%7}, {%8,%9}, {%0,%1,%2,%3};"
                        : "+f"(acc[mf][nf][0]), "+f"(acc[mf][nf][1]),
                          "+f"(acc[mf][nf][2]), "+f"(acc[mf][nf][3])
                        : "r"(a4[mf].x), "r"(a4[mf].y), "r"(a4[mf].z), "r"(a4[mf].w),
                          "r"(b2[nf].x), "r"(b2[nf].y));
                }
        }
        if (kn < K) {
            const int q = p ^ 1;
            float a8[8] = {pa0.x, pa0.y, pa0.z, pa0.w, pa1.x, pa1.y, pa1.z, pa1.w};
            float w8[8] = {pw0.x, pw0.y, pw0.z, pw0.w, pw1.x, pw1.y, pw1.z, pw1.w};
#pragma unroll
            for (int i = 0; i < 8; i++) {
                As[q][a_addr(ldc0 + i, ldr)] = f2tf32(a8[i]);
                Bs[q][b_addr(ldc0 + i, ldr)] = f2tf32(w8[i]);
            }
            __syncthreads();
            p = q;
        }
    }

#pragma unroll
    for (int mf = 0; mf < 4; mf++) {
        const int r0 = bm + m0 + mf * 16 + lq;
        const int r1 = r0 + 8;
        float *crow0, *crow1;
        if (remap == 0) {
            crow0 = C + (size_t)r0 * ldc;
            crow1 = C + (size_t)r1 * ldc;
        } else {
            const int t0 = r0 >> 7, b0 = r0 & 127;
            const int t1 = r1 >> 7, b1 = r1 & 127;
            crow0 = C + (size_t)(b0 * TOUT + t0) * VV;
            crow1 = C + (size_t)(b1 * TOUT + t1) * VV;
        }
#pragma unroll
        for (int nf = 0; nf < 4; nf++) {
            const int c0 = bn + n0 + nf * 8 + (lr4 << 1);
            const float bb0 = bias ? bias[c0] : 0.f;
            const float bb1 = bias ? bias[c0 + 1] : 0.f;
            *(float2*)&crow0[c0] = make_float2(acc[mf][nf][0] + bb0, acc[mf][nf][1] + bb1);
            *(float2*)&crow1[c0] = make_float2(acc[mf][nf][2] + bb0, acc[mf][nf][3] + bb1);
        }
    }
}

// -------- attention: q-proj + scores + softmax + context (block per b) ------
__global__ __launch_bounds__(512) void attn_qctx(
    const float* __restrict__ h,      // [B,H]
    const float* __restrict__ keys,   // [B,S,H]
    const float* __restrict__ feats,  // [B,S,K]
    const float* __restrict__ wq,     // [H,H]
    const float* __restrict__ attv,   // [H]
    float* __restrict__ ctx)          // [B,K]
{
    const int b = blockIdx.x;
    const int tid = threadIdx.x;
    const int lane = tid & 31, warp = tid >> 5;     // 16 warps
    __shared__ float h_s[HH], q_s[HH], v_s[HH], sc[SS];
    __shared__ float red[16];

    h_s[tid] = h[(size_t)b * HH + tid];
    v_s[tid] = attv[tid];
    __syncthreads();

    // q[j] = h . wq[j]  (warp-cooperative, 2 rows per iter for ILP)
    for (int j0 = warp * 2; j0 < HH; j0 += 32) {
        const float* wr = wq + (size_t)j0 * HH;
        float s0 = 0.f, s1 = 0.f;
        for (int k = lane; k < HH; k += 32) {
            const float hv = h_s[k];
            s0 += hv * wr[k];
            s1 += hv * wr[HH + k];
        }
#pragma unroll
        for (int o = 16; o; o >>= 1) {
            s0 += __shfl_xor_sync(0xffffffffu, s0, o);
            s1 += __shfl_xor_sync(0xffffffffu, s1, o);
        }
        if (lane == 0) { q_s[j0] = s0; q_s[j0 + 1] = s1; }
    }
    __syncthreads();

    // scores[s] = sum_k tanh(q[k]+keys[b,s,k]) * v[k]
    for (int s0 = warp * 2; s0 < SS; s0 += 32) {
        const float* kr = keys + ((size_t)b * SS + s0) * HH;
        float acc0 = 0.f, acc1 = 0.f;
        for (int k = lane; k < HH; k += 32) {
            const float q = q_s[k], vv = v_s[k];
            acc0 += fast_tanh(q + kr[k]) * vv;
            acc1 += fast_tanh(q + kr[HH + k]) * vv;
        }
#pragma unroll
        for (int o = 16; o; o >>= 1) {
            acc0 += __shfl_xor_sync(0xffffffffu, acc0, o);
            acc1 += __shfl_xor_sync(0xffffffffu, acc1, o);
        }
        if (lane == 0) { sc[s0] = acc0; sc[s0 + 1] = acc1; }
    }
    __syncthreads();

    // softmax over S=196
    float m = (tid < SS) ? sc[tid] : -1e30f;
#pragma unroll
    for (int o = 16; o; o >>= 1) m = fmaxf(m, __shfl_xor_sync(0xffffffffu, m, o));
    if (lane == 0) red[warp] = m;
    __syncthreads();
    m = red[0];
#pragma unroll
    for (int w = 1; w < 16; w++) m = fmaxf(m, red[w]);

    float e = (tid < SS) ? __expf(sc[tid] - m) : 0.f;
    float ssum = e;
#pragma unroll
    for (int o = 16; o; o >>= 1) ssum += __shfl_xor_sync(0xffffffffu, ssum, o);
    __syncthreads();
    if (lane == 0) red[warp] = ssum;
    __syncthreads();
    float tot = 0.f;
#pragma unroll
    for (int w = 0; w < 16; w++) tot += red[w];
    const float inv = __fdividef(1.0f, tot);
    if (tid < SS) sc[tid] = e * inv;
    __syncthreads();

    // context[k] = sum_s w[s] * feats[b,s,k]
    const float* fb = feats + (size_t)b * SS * KK + tid;
    float acc = 0.f;
#pragma unroll 14
    for (int s = 0; s < SS; s++) acc += sc[s] * fb[(size_t)s * KK];
    ctx[(size_t)b * KK + tid] = acc;
}

// -------- GRU gate combine (torch order r,z,n) --------
__global__ void gru_gates(const float* __restrict__ gi,
                          const float* __restrict__ gh,
                          const float* __restrict__ hprev,
                          float* __restrict__ hnew)
{
    const int idx = blockIdx.x * blockDim.x + threadIdx.x;
    if (idx >= BB * HH) return;
    const int b = idx >> 9, i = idx & 511;
    const float* gib = gi + (size_t)b * G3;
    const float* ghb = gh + (size_t)b * G3;
    const float r = fast_sigmoid(gib[i] + ghb[i]);
    const float z = fast_sigmoid(gib[i + HH] + ghb[i + HH]);
    const float n = fast_tanh(gib[i + 2 * HH] + r * ghb[i + 2 * HH]);
    hnew[idx] = (1.f - z) * n + z * hprev[idx];
}

// -------- launch --------
extern "C" void kernel_launch(void* const* d_in, const int* in_sizes, int n_in,
                              void* d_out, int out_size)
{
    const float* features = (const float*)d_in[0];
    const int*   captions = (const int*)  d_in[1];
    const float* emb      = (const float*)d_in[2];
    const float* fc1_w    = (const float*)d_in[3];
    const float* fc1_b    = (const float*)d_in[4];
    const float* att_wq   = (const float*)d_in[5];
    const float* att_wk   = (const float*)d_in[6];
    const float* att_v    = (const float*)d_in[7];
    const float* fc0_w    = (const float*)d_in[8];
    const float* fc0_b    = (const float*)d_in[9];
    const float* gru_wih  = (const float*)d_in[10];
    const float* gru_whh  = (const float*)d_in[11];
    const float* gru_bih  = (const float*)d_in[12];
    const float* gru_bhh  = (const float*)d_in[13];
    const float* fc2_w    = (const float*)d_in[14];
    const float* fc2_b    = (const float*)d_in[15];
    float* out = (float*)d_out;

    float *keys, *xe, *xproj, *hall, *ctx, *fc0wT, *wcomb, *bcomb, *gix, *gi, *gh;
    cudaGetSymbolAddress((void**)&keys,  g_keys);
    cudaGetSymbolAddress((void**)&xe,    g_xe);
    cudaGetSymbolAddress((void**)&xproj, g_xproj);
    cudaGetSymbolAddress((void**)&hall,  g_hall);
    cudaGetSymbolAddress((void**)&ctx,   g_ctx);
    cudaGetSymbolAddress((void**)&fc0wT, g_fc0wT);
    cudaGetSymbolAddress((void**)&wcomb, g_wcomb);
    cudaGetSymbolAddress((void**)&bcomb, g_bcomb);
    cudaGetSymbolAddress((void**)&gix,   g_gix);
    cudaGetSymbolAddress((void**)&gi,    g_gi);
    cudaGetSymbolAddress((void**)&gh,    g_gh);

    // h0 = 0
    zero_kernel<<<(BB * HH + 255) / 256, 256>>>(hall, BB * HH);

    // x = fc1(emb[captions])
    gather_emb<<<(BB * TT * (HH / 4) + 255) / 256, 256>>>(captions, emb, xe);
    sgemm32p<<<dim3(HH / 32, (BB * TT) / 32), 256>>>(
        xe, fc1_w, fc1_b, xproj, HH, HH, HH, HH);

    // keys_proj = features @ att_wk^T (tensor cores)
    gemm_tf32<<<dim3((BB * SS) / 128, HH / 128), 256>>>(
        features, att_wk, nullptr, keys, KK, HH, 0);

    // one-time GRU-input folding (all fp32):
    //   fc0wT = fc0_w^T ; bcomb = Wih_c @ fc0_b ; wcomb = Wih_c @ fc0_w
    //   gix   = xproj @ Wih_x^T + bih   (all B*TT rows)
    transpose512<<<dim3(16, 16), dim3(32, 8)>>>(fc0_w, fc0wT);
    bcomb_kernel<<<G3 / 4, 128>>>(gru_wih, fc0_b, bcomb);
    sgemm32p<<<dim3(KK / 32, G3 / 32), 256>>>(
        gru_wih + HH, fc0wT, nullptr, wcomb, HH, 2 * HH, KK, KK);
    sgemm32p<<<dim3(G3 / 32, (BB * TT) / 32), 256>>>(
        xproj, gru_wih, gru_bih, gix, HH, HH, 2 * HH, G3);

    // sequential decode: 3 launches per step
    for (int t = 0; t < TOUT; t++) {
        const float* hprev = hall + (size_t)t * BB * HH;
        float* hnext       = hall + (size_t)(t + 1) * BB * HH;
        attn_qctx<<<BB, 512>>>(hprev, keys, features, att_wq, att_v, ctx);
        step_gemm<<<dim3(G3 / 32, BB / 32, 2), 256>>>(
            ctx, hprev, wcomb, gru_whh, bcomb, gru_bhh, gix, t, gi, gh);
        gru_gates<<<(BB * HH + 255) / 256, 256>>>(gi, gh, hprev, hnext);
    }

    // out = h_all[1..15] @ fc2_w^T + fc2_b as ONE (1920,512)x(512,32000) GEMM
    gemm_tf32<<<dim3((TOUT * BB) / 128, VV / 128), 256>>>(
        hall + (size_t)BB * HH, fc2_w, fc2_b, out, HH, 0, 1);
}